// round 1
// baseline (speedup 1.0000x reference)
#include <cuda_runtime.h>
#include <cuda_bf16.h>

// Problem constants
#define B_TOTAL 1024
#define N_IN    1024
#define L_LAYERS 5
#define NPL     2048
#define FANIN   16
#define N_OUT   256

// Tiling
#define TB      4                   // batch elements per block (float4 lane)
#define THREADS 512
#define WIDTH_SM (N_IN + (L_LAYERS - 1) * NPL)   // 9216 nodes kept in smem
#define SMEM_BYTES (WIDTH_SM * TB * sizeof(float))  // 147456 B

__device__ __forceinline__ float tanh_fast(float x) {
    float y;
    asm("tanh.approx.f32 %0, %1;" : "=f"(y) : "f"(x));
    return y;
}

__device__ __forceinline__ float4 fma4(float4 v, float w, float4 acc) {
    acc.x = fmaf(v.x, w, acc.x);
    acc.y = fmaf(v.y, w, acc.y);
    acc.z = fmaf(v.z, w, acc.z);
    acc.w = fmaf(v.w, w, acc.w);
    return acc;
}

__global__ __launch_bounds__(THREADS, 1)
void neat_kernel(const float* __restrict__ inputs,
                 const int*   __restrict__ edge_src,
                 const float* __restrict__ edge_w,
                 const float* __restrict__ biases,
                 float*       __restrict__ out) {
    extern __shared__ float4 vals[];   // vals[node] = {b0,b1,b2,b3}

    const int b0 = blockIdx.x * TB;
    const int t  = threadIdx.x;

    // ---- Load inputs transposed into smem: vals[i] = inputs[b0..b0+3][i] ----
    #pragma unroll 2
    for (int i = t; i < N_IN; i += THREADS) {
        float4 v;
        v.x = inputs[(b0 + 0) * N_IN + i];
        v.y = inputs[(b0 + 1) * N_IN + i];
        v.z = inputs[(b0 + 2) * N_IN + i];
        v.w = inputs[(b0 + 3) * N_IN + i];
        vals[i] = v;
    }
    __syncthreads();

    int base = N_IN;
    for (int l = 0; l < L_LAYERS; ++l) {
        const bool last = (l == L_LAYERS - 1);
        const int n_lo = last ? (NPL - N_OUT) : 0;   // last layer: only needed nodes

        for (int n = n_lo + t; n < NPL; n += THREADS) {
            const long ei = (long)(l * NPL + n);
            const int4*   sp = reinterpret_cast<const int4*>(edge_src) + ei * (FANIN / 4);
            const float4* wp = reinterpret_cast<const float4*>(edge_w) + ei * (FANIN / 4);

            int4   s[4];
            float4 w[4];
            #pragma unroll
            for (int j = 0; j < 4; ++j) { s[j] = sp[j]; w[j] = wp[j]; }

            const float bias = biases[ei];
            float4 acc = make_float4(bias, bias, bias, bias);

            #pragma unroll
            for (int j = 0; j < 4; ++j) {
                acc = fma4(vals[s[j].x], w[j].x, acc);
                acc = fma4(vals[s[j].y], w[j].y, acc);
                acc = fma4(vals[s[j].z], w[j].z, acc);
                acc = fma4(vals[s[j].w], w[j].w, acc);
            }

            if (!last) {
                float4 a;
                a.x = tanh_fast(acc.x);
                a.y = tanh_fast(acc.y);
                a.z = tanh_fast(acc.z);
                a.w = tanh_fast(acc.w);
                vals[base + n] = a;
            } else {
                // accurate sigmoid on the output layer
                const int  c = n - (NPL - N_OUT);
                out[(b0 + 0) * N_OUT + c] = 1.0f / (1.0f + __expf(-acc.x));
                out[(b0 + 1) * N_OUT + c] = 1.0f / (1.0f + __expf(-acc.y));
                out[(b0 + 2) * N_OUT + c] = 1.0f / (1.0f + __expf(-acc.z));
                out[(b0 + 3) * N_OUT + c] = 1.0f / (1.0f + __expf(-acc.w));
            }
        }
        if (!last) __syncthreads();
        base += NPL;
    }
}

extern "C" void kernel_launch(void* const* d_in, const int* in_sizes, int n_in,
                              void* d_out, int out_size) {
    const float* inputs   = (const float*)d_in[0];
    const int*   edge_src = (const int*)  d_in[1];
    const float* edge_w   = (const float*)d_in[2];
    const float* biases   = (const float*)d_in[3];
    float*       out      = (float*)d_out;

    cudaFuncSetAttribute(neat_kernel,
                         cudaFuncAttributeMaxDynamicSharedMemorySize,
                         SMEM_BYTES);

    neat_kernel<<<B_TOTAL / TB, THREADS, SMEM_BYTES>>>(
        inputs, edge_src, edge_w, biases, out);
}

// round 2
// speedup vs baseline: 1.3160x; 1.3160x over previous
#include <cuda_runtime.h>
#include <cuda_fp16.h>

// Problem constants
#define B_TOTAL  1024
#define N_IN     1024
#define L_LAYERS 5
#define NPL      2048
#define FANIN    16
#define N_OUT    256

// Tiling
#define TB       4                    // batch elements per block
#define THREADS  512
#define WIDTH_SM (N_IN + (L_LAYERS - 1) * NPL)   // 9216 nodes kept in smem
#define SMEM_BYTES (WIDTH_SM * 8)                // 9216 * 8B (fp16 x4) = 73728

// 4 batch lanes of one node, packed fp16 (8 bytes -> LDS.64)
struct alignas(8) h4 { __half2 lo, hi; };

__device__ __forceinline__ float tanh_fast(float x) {
    float y;
    asm("tanh.approx.f32 %0, %1;" : "=f"(y) : "f"(x));
    return y;
}

#define GATHER(IDX, W)                                              \
    {                                                               \
        h4 v = vals[(IDX)];                                         \
        float2 p = __half22float2(v.lo);                            \
        float2 q = __half22float2(v.hi);                            \
        acc.x = fmaf(p.x, (W), acc.x);                              \
        acc.y = fmaf(p.y, (W), acc.y);                              \
        acc.z = fmaf(q.x, (W), acc.z);                              \
        acc.w = fmaf(q.y, (W), acc.w);                              \
    }

__global__ __launch_bounds__(THREADS, 2)
void neat_kernel(const float* __restrict__ inputs,
                 const int*   __restrict__ edge_src,
                 const float* __restrict__ edge_w,
                 const float* __restrict__ biases,
                 float*       __restrict__ out) {
    extern __shared__ h4 vals[];   // vals[node] = fp16 {b0,b1,b2,b3}

    const int b0 = blockIdx.x * TB;
    const int t  = threadIdx.x;

    // ---- Load inputs transposed into smem (fp32 -> fp16) ----
    for (int i = t; i < N_IN; i += THREADS) {
        float x0 = inputs[(b0 + 0) * N_IN + i];
        float x1 = inputs[(b0 + 1) * N_IN + i];
        float x2 = inputs[(b0 + 2) * N_IN + i];
        float x3 = inputs[(b0 + 3) * N_IN + i];
        h4 v;
        v.lo = __floats2half2_rn(x0, x1);
        v.hi = __floats2half2_rn(x2, x3);
        vals[i] = v;
    }
    __syncthreads();

    int base = N_IN;
    for (int l = 0; l < L_LAYERS; ++l) {
        const bool last = (l == L_LAYERS - 1);
        const int  n_lo = last ? (NPL - N_OUT) : 0;   // last layer: only needed nodes

        const int4*   sp_l   = reinterpret_cast<const int4*>(edge_src)
                               + (l * NPL) * (FANIN / 4);
        const float4* wp_l   = reinterpret_cast<const float4*>(edge_w)
                               + (l * NPL) * (FANIN / 4);
        const float*  bias_l = biases + l * NPL;

        for (int n = n_lo + t; n < NPL; n += THREADS) {
            const int4*   sp = sp_l + n * (FANIN / 4);
            const float4* wp = wp_l + n * (FANIN / 4);

            const float bias = bias_l[n];
            float4 acc = make_float4(bias, bias, bias, bias);

            #pragma unroll
            for (int j = 0; j < 4; ++j) {
                int4   s = sp[j];
                float4 w = wp[j];
                GATHER(s.x, w.x);
                GATHER(s.y, w.y);
                GATHER(s.z, w.z);
                GATHER(s.w, w.w);
            }

            if (!last) {
                h4 r;
                r.lo = __floats2half2_rn(tanh_fast(acc.x), tanh_fast(acc.y));
                r.hi = __floats2half2_rn(tanh_fast(acc.z), tanh_fast(acc.w));
                vals[base + n] = r;
            } else {
                // accurate fp32 sigmoid on the output layer
                const int c = n - (NPL - N_OUT);
                out[(b0 + 0) * N_OUT + c] = 1.0f / (1.0f + __expf(-acc.x));
                out[(b0 + 1) * N_OUT + c] = 1.0f / (1.0f + __expf(-acc.y));
                out[(b0 + 2) * N_OUT + c] = 1.0f / (1.0f + __expf(-acc.z));
                out[(b0 + 3) * N_OUT + c] = 1.0f / (1.0f + __expf(-acc.w));
            }
        }
        if (!last) __syncthreads();
        base += NPL;
    }
}

extern "C" void kernel_launch(void* const* d_in, const int* in_sizes, int n_in,
                              void* d_out, int out_size) {
    const float* inputs   = (const float*)d_in[0];
    const int*   edge_src = (const int*)  d_in[1];
    const float* edge_w   = (const float*)d_in[2];
    const float* biases   = (const float*)d_in[3];
    float*       out      = (float*)d_out;

    cudaFuncSetAttribute(neat_kernel,
                         cudaFuncAttributeMaxDynamicSharedMemorySize,
                         SMEM_BYTES);

    neat_kernel<<<B_TOTAL / TB, THREADS, SMEM_BYTES>>>(
        inputs, edge_src, edge_w, biases, out);
}

// round 3
// speedup vs baseline: 2.4784x; 1.8832x over previous
#include <cuda_runtime.h>
#include <cuda_fp16.h>

// Problem constants
#define B_TOTAL  1024
#define N_IN     1024
#define L_LAYERS 5
#define NPL      2048
#define FANIN    16
#define N_OUT    256
#define WIDTH    (N_IN + (L_LAYERS - 1) * NPL)   // 9216 stored node rows

// Activation tensor, [node][batch] fp16, L2-resident (18.9 MB)
__device__ __align__(16) __half g_vals[(size_t)WIDTH * B_TOTAL];

// 4 batch lanes packed (8 bytes -> one LDG.64 / STG.64)
struct alignas(8) h4 { __half2 lo, hi; };

__device__ __forceinline__ float tanh_fast(float x) {
    float y;
    asm("tanh.approx.f32 %0, %1;" : "=f"(y) : "f"(x));
    return y;
}

// ---------------------------------------------------------------------------
// Tiled transpose: inputs[b][i] (fp32, 1024x1024) -> g_vals[i][b] (fp16)
// ---------------------------------------------------------------------------
__global__ void transpose_kernel(const float* __restrict__ in) {
    __shared__ float tile[32][33];
    const int it = blockIdx.x;   // i tile
    const int bt = blockIdx.y;   // b tile
    const int tx = threadIdx.x;  // 0..31
    const int ty = threadIdx.y;  // 0..7

    #pragma unroll
    for (int r = 0; r < 4; ++r) {
        int b = bt * 32 + ty + r * 8;
        int i = it * 32 + tx;
        tile[ty + r * 8][tx] = in[b * N_IN + i];   // coalesced read
    }
    __syncthreads();
    #pragma unroll
    for (int r = 0; r < 4; ++r) {
        int i = it * 32 + ty + r * 8;
        int b = bt * 32 + tx;
        g_vals[(size_t)i * B_TOTAL + b] = __float2half(tile[tx][ty + r * 8]);
    }
}

// ---------------------------------------------------------------------------
// One layer. Warp = one node x 128 batch (lane*4). Gather loads are 256B
// coalesced from L2; src/w/bias loads are warp-uniform (broadcast).
// node_lo..node_lo+node_cnt-1 within this layer are computed.
// write_base >= 0: store tanh(act) to g_vals row (write_base + n).
// write_base <  0: final layer -> sigmoid, write to out[b][n - node_lo].
// ---------------------------------------------------------------------------
__global__ __launch_bounds__(256)
void layer_kernel(const int*   __restrict__ src,    // [NPL][FANIN] this layer
                  const float* __restrict__ w,      // [NPL][FANIN]
                  const float* __restrict__ bias,   // [NPL]
                  int node_lo, int write_base,
                  float* __restrict__ out) {
    const int gw   = (blockIdx.x * blockDim.x + threadIdx.x) >> 5;  // global warp
    const int lane = threadIdx.x & 31;
    const int n    = node_lo + (gw >> 3);        // node within layer
    const int b0   = (gw & 7) * 128 + lane * 4;  // first of 4 batch elems

    const int4*   sp = reinterpret_cast<const int4*>(src) + n * (FANIN / 4);
    const float4* wp = reinterpret_cast<const float4*>(w)  + n * (FANIN / 4);

    const float bi = bias[n];
    float4 acc = make_float4(bi, bi, bi, bi);

    #pragma unroll
    for (int j = 0; j < 4; ++j) {
        const int4   s  = sp[j];
        const float4 wv = wp[j];
        #pragma unroll
        for (int k = 0; k < 4; ++k) {
            const int   si = (&s.x)[k];
            const float wk = (&wv.x)[k];
            h4 v = *reinterpret_cast<const h4*>(&g_vals[(size_t)si * B_TOTAL + b0]);
            float2 p = __half22float2(v.lo);
            float2 q = __half22float2(v.hi);
            acc.x = fmaf(p.x, wk, acc.x);
            acc.y = fmaf(p.y, wk, acc.y);
            acc.z = fmaf(q.x, wk, acc.z);
            acc.w = fmaf(q.y, wk, acc.w);
        }
    }

    if (write_base >= 0) {
        h4 r;
        r.lo = __floats2half2_rn(tanh_fast(acc.x), tanh_fast(acc.y));
        r.hi = __floats2half2_rn(tanh_fast(acc.z), tanh_fast(acc.w));
        *reinterpret_cast<h4*>(&g_vals[(size_t)(write_base + n) * B_TOTAL + b0]) = r;
    } else {
        const int c = n - node_lo;   // 0..N_OUT-1
        out[(b0 + 0) * N_OUT + c] = 1.0f / (1.0f + __expf(-acc.x));
        out[(b0 + 1) * N_OUT + c] = 1.0f / (1.0f + __expf(-acc.y));
        out[(b0 + 2) * N_OUT + c] = 1.0f / (1.0f + __expf(-acc.z));
        out[(b0 + 3) * N_OUT + c] = 1.0f / (1.0f + __expf(-acc.w));
    }
}

extern "C" void kernel_launch(void* const* d_in, const int* in_sizes, int n_in,
                              void* d_out, int out_size) {
    const float* inputs   = (const float*)d_in[0];
    const int*   edge_src = (const int*)  d_in[1];
    const float* edge_w   = (const float*)d_in[2];
    const float* biases   = (const float*)d_in[3];
    float*       out      = (float*)d_out;

    // 1) inputs -> g_vals[0..N_IN), transposed to [node][batch] fp16
    transpose_kernel<<<dim3(N_IN / 32, B_TOTAL / 32), dim3(32, 8)>>>(inputs);

    // 2) hidden layers 0..3: full 2048 nodes each, tanh, stored to g_vals
    for (int l = 0; l < L_LAYERS - 1; ++l) {
        layer_kernel<<<NPL, 256>>>(edge_src + (size_t)l * NPL * FANIN,
                                   edge_w   + (size_t)l * NPL * FANIN,
                                   biases   + (size_t)l * NPL,
                                   0, N_IN + l * NPL, out);
    }

    // 3) final layer: only the last N_OUT nodes, sigmoid, write to out
    {
        const int l = L_LAYERS - 1;
        layer_kernel<<<N_OUT, 256>>>(edge_src + (size_t)l * NPL * FANIN,
                                     edge_w   + (size_t)l * NPL * FANIN,
                                     biases   + (size_t)l * NPL,
                                     NPL - N_OUT, -1, out);
    }
}